// round 15
// baseline (speedup 1.0000x reference)
#include <cuda_runtime.h>
#include <stdint.h>

// ============================================================================
// SpecAugment, bit-exact vs JAX threefry2x32 (partitionable mode).
// R15: balanced persistent-style grid. 1184 blocks (=148 SMs x 8 resident);
// block i handles rows [i*5120/1184, (i+1)*5120/1184) -> 4 or 5 rows each,
// perfectly balanced across SMs (R14: 136 SMs had 7 blocks x 5 rows, 12 had
// 6 -> makespan set by stragglers; occ 65.6%). A block's range spans <=2
// batches; prologue computes RNG + two 4000-bit masks for both.
// Memory ops unchanged from R14: v8.b32 evict_last loads, .cs stores.
// ============================================================================

#define BATCH 64
#define NMELS 80
#define TLEN 4000
#define NQ8 (TLEN / 8)         // 500 8-float groups per row
#define NROWS (BATCH * NMELS)  // 5120
#define GRID 1184              // 148 * 8

// ---------------- threefry2x32, constexpr-capable ----------------
struct U2 { uint32_t a, b; };

__host__ __device__ constexpr uint32_t rotl32c(uint32_t x, int d) {
    return (x << d) | (x >> (32 - d));
}

__host__ __device__ constexpr U2 tf2x32(uint32_t k0, uint32_t k1,
                                        uint32_t c0, uint32_t c1) {
    const uint32_t ks0 = k0, ks1 = k1, ks2 = 0x1BD11BDAu ^ k0 ^ k1;
    uint32_t x0 = c0 + ks0, x1 = c1 + ks1;
#define TF_RND(r) { x0 += x1; x1 = rotl32c(x1, r); x1 ^= x0; }
    TF_RND(13) TF_RND(15) TF_RND(26) TF_RND(6)
    x0 += ks1; x1 += ks2 + 1u;
    TF_RND(17) TF_RND(29) TF_RND(16) TF_RND(24)
    x0 += ks2; x1 += ks0 + 2u;
    TF_RND(13) TF_RND(15) TF_RND(26) TF_RND(6)
    x0 += ks0; x1 += ks1 + 3u;
    TF_RND(17) TF_RND(29) TF_RND(16) TF_RND(24)
    x0 += ks1; x1 += ks2 + 4u;
    TF_RND(13) TF_RND(15) TF_RND(26) TF_RND(6)
    x0 += ks2; x1 += ks0 + 5u;
#undef TF_RND
    return U2{x0, x1};
}

// Compile-time key folds: split(key(42), 4) and randint's internal split.
constexpr U2 KFW = tf2x32(0u, 42u, 0u, 0u);            // kf_w
constexpr U2 KFS = tf2x32(0u, 42u, 0u, 1u);            // kf_s
constexpr U2 KTW = tf2x32(0u, 42u, 0u, 2u);            // kt_w
constexpr U2 KTS = tf2x32(0u, 42u, 0u, 3u);            // kt_s
constexpr U2 KLO = tf2x32(KFW.a, KFW.b, 0u, 1u);       // randint lower-bits key

__device__ __forceinline__ uint32_t randbits32(uint32_t k0, uint32_t k1, uint32_t idx) {
    U2 r = tf2x32(k0, k1, 0u, idx);
    return r.a ^ r.b;
}

__device__ __forceinline__ float u32_to_unif(uint32_t bits) {
    return __uint_as_float((bits >> 9) | 0x3f800000u) - 1.0f;
}

// ---------------- 256-bit global memory ops ----------------
struct V8 { uint32_t r[8]; };

__device__ __forceinline__ V8 ldg256_el(const uint32_t* p) {
    V8 v;
    asm("ld.global.nc.L2::evict_last.v8.b32 {%0,%1,%2,%3,%4,%5,%6,%7}, [%8];"
        : "=r"(v.r[0]), "=r"(v.r[1]), "=r"(v.r[2]), "=r"(v.r[3]),
          "=r"(v.r[4]), "=r"(v.r[5]), "=r"(v.r[6]), "=r"(v.r[7])
        : "l"(p));
    return v;
}

__device__ __forceinline__ void stg256_cs(uint32_t* p, const V8& v) {
    asm volatile("st.global.cs.v8.b32 [%0], {%1,%2,%3,%4,%5,%6,%7,%8};"
                 :: "l"(p),
                    "r"(v.r[0]), "r"(v.r[1]), "r"(v.r[2]), "r"(v.r[3]),
                    "r"(v.r[4]), "r"(v.r[5]), "r"(v.r[6]), "r"(v.r[7])
                 : "memory");
}

// ---------------- fused kernel ----------------
__global__ void __launch_bounds__(256, 8)
fused_kernel(const float* __restrict__ mel,
             const int* __restrict__ lengths,
             float* __restrict__ out) {
    __shared__ int s_t0[2][5], s_tl[2][5], s_f0[2][2], s_fl[2][2];
    __shared__ uint32_t s_bits[2][TLEN / 32];   // two 4000-bit masks

    const int tid = threadIdx.x;
    const int bid = blockIdx.x;

    // balanced row range: every block gets 4 or 5 of the 5120 rows
    const int start = (bid * NROWS) / GRID;
    const int end = ((bid + 1) * NROWS) / GRID;
    const int b0 = start / NMELS;
    const int b1 = (end - 1) / NMELS;       // b1 == b0 or b0+1

    // -- RNG draws for up to 2 batches (identical math to verified R1-R14) --
    if (tid < 16) {
        const int grp = tid >> 3;           // 0 -> b0, 1 -> b1
        const int sub = tid & 7;
        const int bb = grp ? b1 : b0;
        if (sub < 5) {
            int j = sub;
            int valid = lengths[bb];
            int mt = (int)((float)valid * 0.05f);
            int max_t = min(25, mt);
            max_t = min(max_t, valid - 1);
            max_t = max(0, max_t);
            uint32_t i = (uint32_t)(bb * 5 + j);
            float ut = u32_to_unif(randbits32(KTW.a, KTW.b, i));
            int t = (int)floorf(ut * (float)(max_t + 1));
            if (valid <= 1) t = 0;
            float ut0 = u32_to_unif(randbits32(KTS.a, KTS.b, i));
            int t0 = (int)floorf(ut0 * (float)(valid - t + 1));
            s_t0[grp][j] = t0;
            s_tl[grp][j] = t;
        } else if (sub < 7) {
            int j = sub - 5;
            uint32_t i = (uint32_t)(bb * 2 + j);
            int f = (int)(randbits32(KLO.a, KLO.b, i) & 15u);
            float uf = u32_to_unif(randbits32(KFS.a, KFS.b, i));
            int f0 = (int)floorf(uf * (float)(NMELS - f + 1));
            s_f0[grp][j] = f0;
            s_fl[grp][j] = f;
        }
    }
    __syncthreads();

    // -- build both 4000-bit time masks via interval spans --
    if (tid < 2 * (TLEN / 32)) {
        const int g = tid >= (TLEN / 32) ? 1 : 0;
        const int w_idx = tid - g * (TLEN / 32);
        const int base = w_idx * 32;
        uint32_t w = 0;
#pragma unroll
        for (int j = 0; j < 5; j++) {
            int lo = max(s_t0[g][j], base);
            int hi = min(s_t0[g][j] + s_tl[g][j], base + 32);
            if (hi > lo)
                w |= (uint32_t)(((1ull << (hi - lo)) - 1ull) << (lo - base));
        }
        s_bits[g][w_idx] = w;
    }
    __syncthreads();

    // -- stream rows [start, end); 2 x 32B groups per thread per row --
    for (int row = start; row < end; row++) {
        const int bb = row / NMELS;
        const int m = row - bb * NMELS;
        const int g = (bb == b0) ? 0 : 1;
        const uint32_t* mrow = reinterpret_cast<const uint32_t*>(mel) + (size_t)row * TLEN;
        uint32_t* orow = reinterpret_cast<uint32_t*>(out) + (size_t)row * TLEN;
        const bool rz = ((unsigned)(m - s_f0[g][0]) < (unsigned)s_fl[g][0]) |
                        ((unsigned)(m - s_f0[g][1]) < (unsigned)s_fl[g][1]);

        if (rz) {
            V8 z;
#pragma unroll
            for (int q = 0; q < 8; q++) z.r[q] = 0u;
#pragma unroll
            for (int k = 0; k < 2; k++) {
                int idx = tid + k * 256;
                if (idx < NQ8)
                    stg256_cs(orow + idx * 8, z);
            }
        } else {
            V8 v[2];
            unsigned mb[2];
            // loads first (front-batched 32B LDGs)
#pragma unroll
            for (int k = 0; k < 2; k++) {
                int idx = tid + k * 256;
                if (idx < NQ8)
                    v[k] = ldg256_el(mrow + idx * 8);
            }
            // mask bytes while loads are in flight
#pragma unroll
            for (int k = 0; k < 2; k++) {
                int idx = tid + k * 256;
                mb[k] = (idx < NQ8)
                    ? (s_bits[g][idx >> 2] >> ((idx & 3) * 8)) & 255u
                    : 0u;
            }
#pragma unroll
            for (int k = 0; k < 2; k++) {
                int idx = tid + k * 256;
                if (idx >= NQ8) continue;
#pragma unroll
                for (int q = 0; q < 8; q++)
                    v[k].r[q] = (mb[k] & (1u << q)) ? 0u : v[k].r[q];
                stg256_cs(orow + idx * 8, v[k]);
            }
        }
    }
}

extern "C" void kernel_launch(void* const* d_in, const int* in_sizes, int n_in,
                              void* d_out, int out_size) {
    const float* mel = (const float*)d_in[0];
    const int* lengths = (const int*)d_in[1];
    float* out = (float*)d_out;

    fused_kernel<<<GRID, 256>>>(mel, lengths, out);
}

// round 16
// speedup vs baseline: 1.0713x; 1.0713x over previous
#include <cuda_runtime.h>
#include <stdint.h>

// ============================================================================
// SpecAugment, bit-exact vs JAX threefry2x32 (partitionable mode).
// FINAL (= R13, best measured: 28.70us warm / 22.53us cold, rel_err 0.0).
// R15's balanced grid raised occupancy but regressed duration -> reverted.
//
// Structure:
//  - single fused kernel, grid = 64 batches x 16 chunks, 5 rows/block,
//    __launch_bounds__(256,8) -> 30 regs, single wave.
//  - prologue: 7 lanes compute the threefry draws (constexpr-folded keys),
//    125 lanes build a 4000-bit time mask in smem via interval spans.
//  - hot loop: 4 float4/thread/row; mel loads ld.global.nc with
//    createpolicy L2::evict_last (keeps the 82MB input L2-resident across
//    graph replays); __stcs stores; freq-masked rows skip loads entirely.
// ============================================================================

#define BATCH 64
#define NMELS 80
#define TLEN 4000
#define NQ (TLEN / 4)          // 1000 float4 groups per row
#define CHUNKS 16
#define ROWS_PER_BLK (NMELS / CHUNKS)   // 5

// ---------------- threefry2x32, constexpr-capable ----------------
struct U2 { uint32_t a, b; };

__host__ __device__ constexpr uint32_t rotl32c(uint32_t x, int d) {
    return (x << d) | (x >> (32 - d));
}

__host__ __device__ constexpr U2 tf2x32(uint32_t k0, uint32_t k1,
                                        uint32_t c0, uint32_t c1) {
    const uint32_t ks0 = k0, ks1 = k1, ks2 = 0x1BD11BDAu ^ k0 ^ k1;
    uint32_t x0 = c0 + ks0, x1 = c1 + ks1;
#define TF_RND(r) { x0 += x1; x1 = rotl32c(x1, r); x1 ^= x0; }
    TF_RND(13) TF_RND(15) TF_RND(26) TF_RND(6)
    x0 += ks1; x1 += ks2 + 1u;
    TF_RND(17) TF_RND(29) TF_RND(16) TF_RND(24)
    x0 += ks2; x1 += ks0 + 2u;
    TF_RND(13) TF_RND(15) TF_RND(26) TF_RND(6)
    x0 += ks0; x1 += ks1 + 3u;
    TF_RND(17) TF_RND(29) TF_RND(16) TF_RND(24)
    x0 += ks1; x1 += ks2 + 4u;
    TF_RND(13) TF_RND(15) TF_RND(26) TF_RND(6)
    x0 += ks2; x1 += ks0 + 5u;
#undef TF_RND
    return U2{x0, x1};
}

// Compile-time key folds: split(key(42), 4) and randint's internal split.
constexpr U2 KFW = tf2x32(0u, 42u, 0u, 0u);            // kf_w
constexpr U2 KFS = tf2x32(0u, 42u, 0u, 1u);            // kf_s
constexpr U2 KTW = tf2x32(0u, 42u, 0u, 2u);            // kt_w
constexpr U2 KTS = tf2x32(0u, 42u, 0u, 3u);            // kt_s
constexpr U2 KLO = tf2x32(KFW.a, KFW.b, 0u, 1u);       // randint lower-bits key

__device__ __forceinline__ uint32_t randbits32(uint32_t k0, uint32_t k1, uint32_t idx) {
    U2 r = tf2x32(k0, k1, 0u, idx);
    return r.a ^ r.b;
}

__device__ __forceinline__ float u32_to_unif(uint32_t bits) {
    return __uint_as_float((bits >> 9) | 0x3f800000u) - 1.0f;
}

// L2 evict_last policy descriptor (uniform; CSE'd to one createpolicy)
__device__ __forceinline__ uint64_t evict_last_policy() {
    uint64_t pol;
    asm("createpolicy.fractional.L2::evict_last.b64 %0, 1.0;" : "=l"(pol));
    return pol;
}

// mel load: read-only, L2 high-retention. NOT volatile: pure load with no
// side effects -> ptxas may reorder/hoist across stores for deeper MLP.
__device__ __forceinline__ float4 ldg_evict_last(const float4* p, uint64_t pol) {
    float4 v;
    asm("ld.global.nc.L2::cache_hint.v4.f32 {%0, %1, %2, %3}, [%4], %5;"
        : "=f"(v.x), "=f"(v.y), "=f"(v.z), "=f"(v.w)
        : "l"(p), "l"(pol));
    return v;
}

// ---------------- fused kernel ----------------
__global__ void __launch_bounds__(256, 8)
fused_kernel(const float* __restrict__ mel,
             const int* __restrict__ lengths,
             float* __restrict__ out) {
    __shared__ int s_t0[5], s_tl[5], s_f0[2], s_fl[2];
    __shared__ uint32_t s_bits[NQ / 8];   // 4000 bits = 125 words

    const int b = blockIdx.x >> 4;        // batch
    const int chunk = blockIdx.x & 15;    // 5-row chunk within batch
    const int tid = threadIdx.x;

    // -- RNG draws (identical math across all verified rounds) --
    if (tid < 5) {
        int j = tid;
        int valid = lengths[b];
        int mt = (int)((float)valid * 0.05f);
        int max_t = min(25, mt);
        max_t = min(max_t, valid - 1);
        max_t = max(0, max_t);
        uint32_t i = (uint32_t)(b * 5 + j);
        float ut = u32_to_unif(randbits32(KTW.a, KTW.b, i));
        int t = (int)floorf(ut * (float)(max_t + 1));
        if (valid <= 1) t = 0;
        float ut0 = u32_to_unif(randbits32(KTS.a, KTS.b, i));
        int t0 = (int)floorf(ut0 * (float)(valid - t + 1));
        s_t0[j] = t0;
        s_tl[j] = t;
    } else if (tid < 7) {
        int j = tid - 5;
        uint32_t i = (uint32_t)(b * 2 + j);
        int f = (int)(randbits32(KLO.a, KLO.b, i) & 15u);
        float uf = u32_to_unif(randbits32(KFS.a, KFS.b, i));
        int f0 = (int)floorf(uf * (float)(NMELS - f + 1));
        s_f0[j] = f0;
        s_fl[j] = f;
    }
    __syncthreads();

    // -- build 4000-bit time mask via interval spans --
    if (tid < NQ / 8) {
        const int base = tid * 32;
        uint32_t w = 0;
#pragma unroll
        for (int j = 0; j < 5; j++) {
            int lo = max(s_t0[j], base);
            int hi = min(s_t0[j] + s_tl[j], base + 32);
            if (hi > lo)
                w |= (uint32_t)(((1ull << (hi - lo)) - 1ull) << (lo - base));
        }
        s_bits[tid] = w;
    }
    __syncthreads();

    const int f00 = s_f0[0], fl0 = s_fl[0], f01 = s_f0[1], fl1 = s_fl[1];
    const uint64_t pol = evict_last_policy();

    // -- stream 5 rows --
#pragma unroll
    for (int r = 0; r < ROWS_PER_BLK; r++) {
        const int m = chunk * ROWS_PER_BLK + r;
        const int row = b * NMELS + m;
        const float* mrow = mel + (size_t)row * TLEN;
        float* orow = out + (size_t)row * TLEN;
        const bool rz = ((unsigned)(m - f00) < (unsigned)fl0) |
                        ((unsigned)(m - f01) < (unsigned)fl1);

        if (rz) {
            const float4 z = make_float4(0.f, 0.f, 0.f, 0.f);
#pragma unroll
            for (int k = 0; k < 4; k++) {
                int idx = tid + k * 256;
                if (idx < NQ)
                    __stcs(reinterpret_cast<float4*>(orow + idx * 4), z);
            }
        } else {
            unsigned nib[4];
            float4 v[4];
            // data loads first (front-batched LDGs)
#pragma unroll
            for (int k = 0; k < 4; k++) {
                int idx = tid + k * 256;
                if (idx < NQ)
                    v[k] = ldg_evict_last(reinterpret_cast<const float4*>(mrow + idx * 4), pol);
            }
            // mask nibbles while loads are in flight
#pragma unroll
            for (int k = 0; k < 4; k++) {
                int idx = tid + k * 256;
                nib[k] = (idx < NQ)
                    ? (s_bits[idx >> 3] >> ((idx & 7) * 4)) & 15u
                    : 0u;
            }
#pragma unroll
            for (int k = 0; k < 4; k++) {
                int idx = tid + k * 256;
                if (idx >= NQ) continue;
                v[k].x = (nib[k] & 1u) ? 0.f : v[k].x;
                v[k].y = (nib[k] & 2u) ? 0.f : v[k].y;
                v[k].z = (nib[k] & 4u) ? 0.f : v[k].z;
                v[k].w = (nib[k] & 8u) ? 0.f : v[k].w;
                __stcs(reinterpret_cast<float4*>(orow + idx * 4), v[k]);
            }
        }
    }
}

extern "C" void kernel_launch(void* const* d_in, const int* in_sizes, int n_in,
                              void* d_out, int out_size) {
    const float* mel = (const float*)d_in[0];
    const int* lengths = (const int*)d_in[1];
    float* out = (float*)d_out;

    fused_kernel<<<BATCH * CHUNKS, 256>>>(mel, lengths, out);
}